// round 5
// baseline (speedup 1.0000x reference)
#include <cuda_runtime.h>
#include <cuda_bf16.h>

#define N_NODES    100000
#define OUTPUT_DIM 128
#define KEEP_INV   (1.0f / 0.9f)

// Static device scratch (no allocations allowed)
__device__ int g_mask_mode;              // 0 = uint8/bool, 1 = int32, 2 = float32
__device__ int g_row_start[N_NODES + 1]; // CSR row pointers

// ---------------------------------------------------------------------------
// Kernel 1 (fused): build CSR row_start from sorted COO rows AND, in block 0,
// classify the keep_mask storage dtype from byte statistics.
//
// rowptr: row_start[r] = first i with rows[i] >= r ; row_start[N] = nnz.
// detect (block 0 only, all 256 threads):
//   keep_prob = 0.9 =>
//     uint8 layout  -> ~90% of first 1024 bytes equal 0x01
//     int32 layout  -> ints==1 ~90%, bytes==1 only ~22%
//     float32 layout-> floats==1.0f ~90%, bytes==1 ~0%
// Deterministic: same input -> same result every launch.
// ---------------------------------------------------------------------------
__global__ void __launch_bounds__(256)
rowptr_and_detect_kernel(const int* __restrict__ rows,
                         const unsigned char* __restrict__ m,
                         int nnz)
{
    const int i = blockIdx.x * blockDim.x + threadIdx.x;

    // ---- CSR row pointers (thread-per-nnz) ----
    if (i < nnz) {
        const int r = rows[i];
        const int rprev = (i == 0) ? -1 : rows[i - 1];
        for (int x = rprev + 1; x <= r; ++x) g_row_start[x] = i;
        if (i == nnz - 1) {
            for (int x = r + 1; x <= N_NODES; ++x) g_row_start[x] = nnz;
        }
    }

    // ---- mask dtype detection (block 0 only) ----
    if (blockIdx.x == 0) {
        const int n = nnz < 1024 ? nnz : 1024;
        const int tid = threadIdx.x;
        const int*   mi = (const int*)m;
        const float* mf = (const float*)m;

        int u8 = 0, i32 = 0, f32 = 0;
        #pragma unroll
        for (int k = 0; k < 4; ++k) {
            int s = tid + k * 256;
            if (s < n) {
                if (m[s]  == 1)    u8++;
                if (mi[s] == 1)    i32++;
                if (mf[s] == 1.0f) f32++;
            }
        }
        #pragma unroll
        for (int off = 16; off > 0; off >>= 1) {
            u8  += __shfl_down_sync(0xffffffffu, u8,  off);
            i32 += __shfl_down_sync(0xffffffffu, i32, off);
            f32 += __shfl_down_sync(0xffffffffu, f32, off);
        }
        __shared__ int s_u8[8], s_i32[8], s_f32[8];
        const int wid = tid >> 5, lane = tid & 31;
        if (lane == 0) { s_u8[wid] = u8; s_i32[wid] = i32; s_f32[wid] = f32; }
        __syncthreads();
        if (tid == 0) {
            int tu8 = 0, ti32 = 0, tf32 = 0;
            #pragma unroll
            for (int w = 0; w < 8; ++w) { tu8 += s_u8[w]; ti32 += s_i32[w]; tf32 += s_f32[w]; }
            int mode;
            if (tu8 * 4 > n * 3)        mode = 0;   // byte mask
            else if (ti32 * 4 > n * 3)  mode = 1;   // int32 mask
            else                        mode = 2;   // float32 mask
            g_mask_mode = mode;
        }
    }
}

// ---------------------------------------------------------------------------
// Kernel 2: one warp per output row, lane l owns output columns [4l, 4l+4).
//
// Staging: lanes load up to 32 nnz (coalesced value/col/mask reads), apply
// dropout, then WARP-COMPACT the kept entries into smem via ballot+popc —
// the inner loop sees only live nnz (no branch, ~10% fewer iterations).
// Each kept entry is a packed float2 (v_scaled, col-as-float-bits) so the
// inner loop does ONE broadcast LDS.64 per nnz instead of two SHFLs.
//
// Inner loop is unrolled x4 with 4 independent accumulators so 4 W-row
// gathers (512B each, coalesced float4 across the warp) are in flight
// simultaneously -> exposed L2 latency / 4.
//
// Exclusive row ownership -> plain float4 store, bias fused, no atomics.
// ---------------------------------------------------------------------------
__global__ void __launch_bounds__(256)
spmm_warp_per_row_kernel(const float* __restrict__ values,
                         const int*   __restrict__ cols,
                         const void*  __restrict__ mask,
                         const float4* __restrict__ W4,     // [INPUT_DIM][32] float4
                         const float4* __restrict__ bias4,  // [32] float4
                         float4* __restrict__ out4)         // [N_NODES][32] float4
{
    const int warp  = (blockIdx.x * blockDim.x + threadIdx.x) >> 5;
    const int lane  = threadIdx.x & 31;
    const int wloc  = threadIdx.x >> 5;          // warp index within block
    if (warp >= N_NODES) return;

    __shared__ float2 stage[8][32];              // per-warp compacted (v, colbits)

    const int s = g_row_start[warp];
    const int e = g_row_start[warp + 1];
    const int mode = g_mask_mode;

    float4 a0 = bias4[lane];
    float4 a1 = make_float4(0.f, 0.f, 0.f, 0.f);
    float4 a2 = make_float4(0.f, 0.f, 0.f, 0.f);
    float4 a3 = make_float4(0.f, 0.f, 0.f, 0.f);

    for (int base = s; base < e; base += 32) {
        const int idx = base + lane;
        bool keep = false;
        float v = 0.0f;
        int   c = 0;
        if (idx < e) {
            v = values[idx];
            c = cols[idx];
            if (mode == 0)      keep = ((const unsigned char*)mask)[idx] != 0;
            else if (mode == 1) keep = ((const int*)mask)[idx] != 0;
            else                keep = ((const float*)mask)[idx] != 0.0f;
        }
        const unsigned ballot = __ballot_sync(0xffffffffu, keep);
        if (keep) {
            const int pos = __popc(ballot & ((1u << lane) - 1u));
            stage[wloc][pos] = make_float2(v * KEEP_INV, __int_as_float(c));
        }
        const int cnt = __popc(ballot);
        __syncwarp();

        int k = 0;
        for (; k + 4 <= cnt; k += 4) {
            const float2 e0 = stage[wloc][k + 0];
            const float2 e1 = stage[wloc][k + 1];
            const float2 e2 = stage[wloc][k + 2];
            const float2 e3 = stage[wloc][k + 3];
            const float4 w0 = W4[__float_as_int(e0.y) * 32 + lane];
            const float4 w1 = W4[__float_as_int(e1.y) * 32 + lane];
            const float4 w2 = W4[__float_as_int(e2.y) * 32 + lane];
            const float4 w3 = W4[__float_as_int(e3.y) * 32 + lane];
            a0.x += e0.x * w0.x; a0.y += e0.x * w0.y; a0.z += e0.x * w0.z; a0.w += e0.x * w0.w;
            a1.x += e1.x * w1.x; a1.y += e1.x * w1.y; a1.z += e1.x * w1.z; a1.w += e1.x * w1.w;
            a2.x += e2.x * w2.x; a2.y += e2.x * w2.y; a2.z += e2.x * w2.z; a2.w += e2.x * w2.w;
            a3.x += e3.x * w3.x; a3.y += e3.x * w3.y; a3.z += e3.x * w3.z; a3.w += e3.x * w3.w;
        }
        for (; k < cnt; ++k) {
            const float2 e0 = stage[wloc][k];
            const float4 w0 = W4[__float_as_int(e0.y) * 32 + lane];
            a0.x += e0.x * w0.x; a0.y += e0.x * w0.y; a0.z += e0.x * w0.z; a0.w += e0.x * w0.w;
        }
        __syncwarp();
    }

    float4 acc;
    acc.x = (a0.x + a1.x) + (a2.x + a3.x);
    acc.y = (a0.y + a1.y) + (a2.y + a3.y);
    acc.z = (a0.z + a1.z) + (a2.z + a3.z);
    acc.w = (a0.w + a1.w) + (a2.w + a3.w);
    out4[warp * 32 + lane] = acc;                // 512B coalesced per warp
}

// ---------------------------------------------------------------------------
// kernel_launch — inputs per setup_inputs() order:
//   0: values  float32 [NNZ]
//   1: rows    int32   [NNZ] (sorted)
//   2: cols    int32   [NNZ]
//   3: keep_mask (bool-ish, dtype auto-detected)
//   4: weights float32 [INPUT_DIM, 128]
//   5: bias    float32 [128]
// ---------------------------------------------------------------------------
extern "C" void kernel_launch(void* const* d_in, const int* in_sizes, int n_in,
                              void* d_out, int out_size)
{
    const float* values = (const float*)d_in[0];
    const int*   rows   = (const int*)  d_in[1];
    const int*   cols   = (const int*)  d_in[2];
    const void*  mask   =               d_in[3];
    const float4* W4    = (const float4*)d_in[4];
    const float4* bias4 = (const float4*)d_in[5];
    float4* out4        = (float4*)d_out;

    const int nnz = in_sizes[0];

    {
        int threads = 256;
        int blocks = (nnz + threads - 1) / threads;
        rowptr_and_detect_kernel<<<blocks, threads>>>(
            rows, (const unsigned char*)mask, nnz);
    }

    {
        const int warps_per_block = 8;                 // 256 threads
        int blocks = (N_NODES + warps_per_block - 1) / warps_per_block;
        spmm_warp_per_row_kernel<<<blocks, 256>>>(values, cols, mask, W4, bias4, out4);
    }
}